// round 1
// baseline (speedup 1.0000x reference)
#include <cuda_runtime.h>
#include <math.h>

// ---------------- problem constants ----------------
#define NN 10000
#define EE 320000
#define HH 128       // hidden = filters = 128
#define GG 50        // gaussians
#define LL 6         // layers
#define KTAB 4096    // distance-table resolution
#define PTS 16       // grid points per table-build block

#define DMAXT 8.6605f                       // > sqrt(75) max distance
#define TABSCALE ((float)(KTAB - 1) / DMAXT)
#define DSTEP (DMAXT / (float)(KTAB - 1))
#define GSTEP (10.0f / 49.0f)               // gaussian offset spacing
#define GCOEFF (-0.5f / (GSTEP * GSTEP))
#define LN2F 0.6931471805599453f
#define PIF 3.14159265358979323846f

// ---------------- scratch (static device allocs) ----------------
__device__ float g_table[LL * KTAB * HH];   // Wf(d) tables, 12.6 MB
__device__ float g_x[NN * HH];              // lin1 output
__device__ float g_agg[NN * HH];            // aggregated messages
__device__ float g_u[NN * HH];              // ssp(lin2) output
__device__ int   g_deg[NN];
__device__ int   g_start[NN + 1];           // CSR row pointers (by target)
__device__ int   g_cursor[NN];
__device__ int   g_um[EE];                  // unsorted packed (src | k<<14)
__device__ float g_ut[EE];                  // unsorted interp frac
__device__ int   g_sm[EE];                  // CSR-sorted packed meta
__device__ float g_st[EE];                  // CSR-sorted interp frac

__device__ __forceinline__ float sspf(float v) {
    // softplus(v) - ln2
    float sp = (v > 20.f) ? v : log1pf(expf(v));
    return sp - LN2F;
}

// ---------------- Wf(d) table build ----------------
// One block handles PTS grid points of one layer.
__global__ void __launch_bounds__(128) k_table(
    const float* __restrict__ w1, const float* __restrict__ b1,
    const float* __restrict__ w2, const float* __restrict__ b2)
{
    __shared__ float ea[PTS][GG];
    __shared__ float t1[PTS][HH];
    const int l  = blockIdx.y;
    const int k0 = blockIdx.x * PTS;
    const int f  = threadIdx.x;

    for (int idx = f; idx < PTS * GG; idx += 128) {
        int p = idx / GG, g = idx % GG;
        float d  = (float)(k0 + p) * DSTEP;
        float dd = d - (float)g * GSTEP;
        ea[p][g] = expf(GCOEFF * dd * dd);
    }
    __syncthreads();

    float acc[PTS];
#pragma unroll
    for (int p = 0; p < PTS; p++) acc[p] = 0.f;
    const float* W1 = w1 + l * GG * HH;
    for (int g = 0; g < GG; g++) {
        float w = W1[g * HH + f];
#pragma unroll
        for (int p = 0; p < PTS; p++) acc[p] += ea[p][g] * w;
    }
    float bb = b1[l * HH + f];
#pragma unroll
    for (int p = 0; p < PTS; p++) t1[p][f] = sspf(acc[p] + bb);
    __syncthreads();

#pragma unroll
    for (int p = 0; p < PTS; p++) acc[p] = 0.f;
    const float* W2 = w2 + l * HH * HH;
    for (int ff = 0; ff < HH; ff++) {
        float w = W2[ff * HH + f];
#pragma unroll
        for (int p = 0; p < PTS; p++) acc[p] += t1[p][ff] * w;
    }
    float b2v = b2[l * HH + f];
#pragma unroll
    for (int p = 0; p < PTS; p++) {
        float d = (float)(k0 + p) * DSTEP;
        float C = 0.5f * (cosf(d * (PIF / 10.f)) + 1.f);
        g_table[(size_t)(l * KTAB + k0 + p) * HH + f] = (acc[p] + b2v) * C;
    }
}

// ---------------- CSR build ----------------
__global__ void k_zero(int n) {
    int i = blockIdx.x * blockDim.x + threadIdx.x;
    if (i < n) g_deg[i] = 0;
}

__global__ void k_prep(const int* __restrict__ ei, const float* __restrict__ pos, int E) {
    int e = blockIdx.x * blockDim.x + threadIdx.x;
    if (e >= E) return;
    int r = ei[e], c = ei[E + e];
    float dx = pos[r * 3 + 0] - pos[c * 3 + 0];
    float dy = pos[r * 3 + 1] - pos[c * 3 + 1];
    float dz = pos[r * 3 + 2] - pos[c * 3 + 2];
    float d = sqrtf(dx * dx + dy * dy + dz * dz);
    float u = d * TABSCALE;
    int k = (int)u;
    if (k > KTAB - 2) k = KTAB - 2;
    if (k < 0) k = 0;
    float t = u - (float)k;
    g_um[e] = r | (k << 14);   // src < 16384, k < 4096
    g_ut[e] = t;
    atomicAdd(&g_deg[c], 1);
}

__global__ void __launch_bounds__(1024) k_scan(int n) {
    __shared__ int s[1024];
    const int PER = 10;  // covers 10240 >= NN
    int t = threadIdx.x;
    int base = t * PER;
    int local[PER];
    int sum = 0;
#pragma unroll
    for (int i = 0; i < PER; i++) {
        int v = (base + i < n) ? g_deg[base + i] : 0;
        local[i] = sum;
        sum += v;
    }
    s[t] = sum;
    __syncthreads();
    for (int off = 1; off < 1024; off <<= 1) {
        int v = s[t];
        if (t >= off) v += s[t - off];
        __syncthreads();
        s[t] = v;
        __syncthreads();
    }
    int offset = s[t] - sum;  // exclusive prefix
#pragma unroll
    for (int i = 0; i < PER; i++) {
        if (base + i < n) {
            int st = offset + local[i];
            g_start[base + i]  = st;
            g_cursor[base + i] = st;
        }
    }
    if (t == 1023) g_start[n] = s[1023];
}

__global__ void k_scatter(const int* __restrict__ ei, int E) {
    int e = blockIdx.x * blockDim.x + threadIdx.x;
    if (e >= E) return;
    int c = ei[E + e];
    int p = atomicAdd(&g_cursor[c], 1);
    g_sm[p] = g_um[e];
    g_st[p] = g_ut[e];
}

// ---------------- embedding ----------------
__global__ void k_embed(const int* __restrict__ z, const float* __restrict__ emb,
                        float* __restrict__ h, int N) {
    int idx = blockIdx.x * blockDim.x + threadIdx.x;  // over N*32 float4
    if (idx >= N * 32) return;
    int n = idx >> 5, q = idx & 31;
    ((float4*)h)[idx] = ((const float4*)emb)[z[n] * 32 + q];
}

// ---------------- message aggregation (gather, no atomics) ----------------
// one warp per target node; lane handles 4 features
__global__ void __launch_bounds__(256) k_agg(int l, int N) {
    int warp = (blockIdx.x * 256 + threadIdx.x) >> 5;
    int lane = threadIdx.x & 31;
    if (warp >= N) return;
    const float* __restrict__ tab = g_table + (size_t)l * KTAB * HH;
    int beg = g_start[warp], end = g_start[warp + 1];
    float4 acc = make_float4(0.f, 0.f, 0.f, 0.f);
    for (int e0 = beg; e0 < end; e0 += 32) {
        int idx = e0 + lane;
        int m = 0;
        float tt = 0.f;
        if (idx < end) { m = g_sm[idx]; tt = g_st[idx]; }
        int cnt = min(32, end - e0);
        for (int j = 0; j < cnt; j++) {
            int   mj = __shfl_sync(0xffffffffu, m, j);
            float tj = __shfl_sync(0xffffffffu, tt, j);
            int src = mj & 0x3FFF;
            int k   = mj >> 14;
            const float4 xv = *(const float4*)(g_x + (size_t)src * HH + lane * 4);
            const float4 w0 = *(const float4*)(tab + (size_t)k * HH + lane * 4);
            const float4 w1 = *(const float4*)(tab + (size_t)(k + 1) * HH + lane * 4);
            acc.x += xv.x * (w0.x + tj * (w1.x - w0.x));
            acc.y += xv.y * (w0.y + tj * (w1.y - w0.y));
            acc.z += xv.z * (w0.z + tj * (w1.z - w0.z));
            acc.w += xv.w * (w0.w + tj * (w1.w - w0.w));
        }
    }
    *(float4*)(g_agg + (size_t)warp * HH + lane * 4) = acc;
}

// ---------------- 128-wide fp32 GEMM, M x 128 x 128 ----------------
// MODE 0: g_x   = h   @ B               (h passed as hbuf)
// MODE 1: g_u   = ssp(g_agg @ B + bias)
// MODE 2: hbuf += g_u @ B + bias        (residual update of h)
template <int MODE>
__global__ void __launch_bounds__(256) gemm128(
    const float* __restrict__ B, const float* __restrict__ bias,
    float* __restrict__ hbuf, int M)
{
    __shared__ float As[64][32];
    __shared__ float Bs[32][128];
    const int tid = threadIdx.x;
    const int tx = tid & 31;   // col group (4 cols each)
    const int ty = tid >> 5;   // row group (8 rows each)
    const int m0 = blockIdx.x * 64;

    const float* A = (MODE == 0) ? hbuf : (MODE == 1 ? g_agg : g_u);

    float acc[8][4];
#pragma unroll
    for (int i = 0; i < 8; i++)
#pragma unroll
        for (int j = 0; j < 4; j++) acc[i][j] = 0.f;

    for (int k0 = 0; k0 < HH; k0 += 32) {
        // load A tile 64x32 (512 float4)
#pragma unroll
        for (int i = 0; i < 2; i++) {
            int lin = i * 256 + tid;
            int r = lin >> 3, k4 = lin & 7;
            int gr = m0 + r;
            float4 v = make_float4(0.f, 0.f, 0.f, 0.f);
            if (gr < M) v = *(const float4*)(A + (size_t)gr * HH + k0 + k4 * 4);
            *(float4*)&As[r][k4 * 4] = v;
        }
        // load B tile 32x128 (1024 float4)
#pragma unroll
        for (int i = 0; i < 4; i++) {
            int lin = i * 256 + tid;
            int kk = lin >> 5, c4 = lin & 31;
            *(float4*)&Bs[kk][c4 * 4] =
                *(const float4*)(B + (size_t)(k0 + kk) * HH + c4 * 4);
        }
        __syncthreads();
#pragma unroll
        for (int kk = 0; kk < 32; kk++) {
            float4 b = *(float4*)&Bs[kk][tx * 4];
#pragma unroll
            for (int i = 0; i < 8; i++) {
                float a = As[ty * 8 + i][kk];
                acc[i][0] += a * b.x;
                acc[i][1] += a * b.y;
                acc[i][2] += a * b.z;
                acc[i][3] += a * b.w;
            }
        }
        __syncthreads();
    }

    float4 bi = make_float4(0.f, 0.f, 0.f, 0.f);
    if (MODE >= 1) bi = *(const float4*)(bias + tx * 4);
#pragma unroll
    for (int i = 0; i < 8; i++) {
        int r = m0 + ty * 8 + i;
        if (r >= M) break;
        float4 v;
        v.x = acc[i][0] + bi.x;
        v.y = acc[i][1] + bi.y;
        v.z = acc[i][2] + bi.z;
        v.w = acc[i][3] + bi.w;
        if (MODE == 1) {
            v.x = sspf(v.x); v.y = sspf(v.y); v.z = sspf(v.z); v.w = sspf(v.w);
        }
        float* outp = (MODE == 0) ? (g_x + (size_t)r * HH + tx * 4)
                    : (MODE == 1) ? (g_u + (size_t)r * HH + tx * 4)
                                  : (hbuf + (size_t)r * HH + tx * 4);
        if (MODE == 2) {
            float4 o = *(float4*)outp;
            v.x += o.x; v.y += o.y; v.z += o.z; v.w += o.w;
        }
        *(float4*)outp = v;
    }
}

// ---------------- launch ----------------
extern "C" void kernel_launch(void* const* d_in, const int* in_sizes, int n_in,
                              void* d_out, int out_size)
{
    const int*   z      = (const int*)d_in[0];
    const float* pos    = (const float*)d_in[1];
    const int*   ei     = (const int*)d_in[2];
    const float* emb    = (const float*)d_in[3];
    const float* mlp_w1 = (const float*)d_in[4];
    const float* mlp_b1 = (const float*)d_in[5];
    const float* mlp_w2 = (const float*)d_in[6];
    const float* mlp_b2 = (const float*)d_in[7];
    const float* lin1_w = (const float*)d_in[8];
    const float* lin2_w = (const float*)d_in[9];
    const float* lin2_b = (const float*)d_in[10];
    const float* lin_w  = (const float*)d_in[11];
    const float* lin_b  = (const float*)d_in[12];

    const int N = in_sizes[0];
    const int E = in_sizes[2] / 2;
    float* h = (float*)d_out;

    k_zero<<<(N + 255) / 256, 256>>>(N);
    dim3 tg(KTAB / PTS, LL);
    k_table<<<tg, 128>>>(mlp_w1, mlp_b1, mlp_w2, mlp_b2);
    k_prep<<<(E + 255) / 256, 256>>>(ei, pos, E);
    k_scan<<<1, 1024>>>(N);
    k_scatter<<<(E + 255) / 256, 256>>>(ei, E);
    k_embed<<<(N * 32 + 255) / 256, 256>>>(z, emb, h, N);

    const int gb = (N + 63) / 64;
    const int ga = (N * 32 + 255) / 256;  // one warp per node
    for (int l = 0; l < LL; l++) {
        gemm128<0><<<gb, 256>>>(lin1_w + (size_t)l * HH * HH, nullptr, h, N);
        k_agg<<<ga, 256>>>(l, N);
        gemm128<1><<<gb, 256>>>(lin2_w + (size_t)l * HH * HH, lin2_b + (size_t)l * HH, h, N);
        gemm128<2><<<gb, 256>>>(lin_w + (size_t)l * HH * HH, lin_b + (size_t)l * HH, h, N);
    }
}

// round 4
// speedup vs baseline: 1.1188x; 1.1188x over previous
#include <cuda_runtime.h>
#include <cuda_fp16.h>
#include <mma.h>
#include <math.h>

using namespace nvcuda;

// ---------------- problem constants ----------------
#define NN 10000
#define EE 320000
#define HH 128       // hidden = filters = 128
#define GG 50        // gaussians
#define LL 6         // layers
#define KTAB 4096    // distance-table resolution
#define PTS 16       // grid points per table-build block

#define DMAXT 8.6605f                       // > sqrt(75) max distance
#define TABSCALE ((float)(KTAB - 1) / DMAXT)
#define DSTEP (DMAXT / (float)(KTAB - 1))
#define GSTEP (10.0f / 49.0f)               // gaussian offset spacing
#define GCOEFF (-0.5f / (GSTEP * GSTEP))
#define LN2F 0.6931471805599453f
#define PIF 3.14159265358979323846f

// ---------------- scratch (static device allocs) ----------------
__device__ __half g_tab[LL * KTAB * HH];    // Wf(d) tables, fp16, 6.3 MB
__device__ __half g_xh[NN * HH];            // lin1 output (fp16)
__device__ __half g_aggh[NN * HH];          // aggregated messages (fp16)
__device__ __half g_uh[NN * HH];            // ssp(lin2) output (fp16)
__device__ __half g_hh[NN * HH];            // fp16 copy of h (MMA A operand)
__device__ __half g_w1t[LL * HH * HH];      // lin1_w^T fp16  [l][n][k]
__device__ __half g_w2t[LL * HH * HH];      // lin2_w^T fp16
__device__ __half g_w3t[LL * HH * HH];      // lin_w^T  fp16
__device__ int    g_deg[NN];
__device__ int    g_start[NN + 1];          // CSR row pointers (by target)
__device__ int    g_cursor[NN];
__device__ int    g_um[EE];                 // unsorted packed (src | k<<14)
__device__ float  g_ut[EE];                 // unsorted interp frac
__device__ int    g_sm[EE];                 // CSR-sorted packed meta
__device__ float  g_st[EE];                 // CSR-sorted interp frac

__device__ __forceinline__ float sspf(float v) {
    float sp = (v > 20.f) ? v : log1pf(expf(v));
    return sp - LN2F;
}

// ---------------- Wf(d) table build (fp32 compute, fp16 store) ----------------
__global__ void __launch_bounds__(128) k_table(
    const float* __restrict__ w1, const float* __restrict__ b1,
    const float* __restrict__ w2, const float* __restrict__ b2)
{
    __shared__ float ea[PTS][GG];
    __shared__ float t1[PTS][HH];
    const int l  = blockIdx.y;
    const int k0 = blockIdx.x * PTS;
    const int f  = threadIdx.x;

    for (int idx = f; idx < PTS * GG; idx += 128) {
        int p = idx / GG, g = idx % GG;
        float d  = (float)(k0 + p) * DSTEP;
        float dd = d - (float)g * GSTEP;
        ea[p][g] = expf(GCOEFF * dd * dd);
    }
    __syncthreads();

    float acc[PTS];
#pragma unroll
    for (int p = 0; p < PTS; p++) acc[p] = 0.f;
    const float* W1 = w1 + l * GG * HH;
    for (int g = 0; g < GG; g++) {
        float w = W1[g * HH + f];
#pragma unroll
        for (int p = 0; p < PTS; p++) acc[p] += ea[p][g] * w;
    }
    float bb = b1[l * HH + f];
#pragma unroll
    for (int p = 0; p < PTS; p++) t1[p][f] = sspf(acc[p] + bb);
    __syncthreads();

#pragma unroll
    for (int p = 0; p < PTS; p++) acc[p] = 0.f;
    const float* W2 = w2 + l * HH * HH;
    for (int ff = 0; ff < HH; ff++) {
        float w = W2[ff * HH + f];
#pragma unroll
        for (int p = 0; p < PTS; p++) acc[p] += t1[p][ff] * w;
    }
    float b2v = b2[l * HH + f];
#pragma unroll
    for (int p = 0; p < PTS; p++) {
        float d = (float)(k0 + p) * DSTEP;
        float C = 0.5f * (cosf(d * (PIF / 10.f)) + 1.f);
        g_tab[(size_t)(l * KTAB + k0 + p) * HH + f] =
            __float2half((acc[p] + b2v) * C);
    }
}

// ---------------- weight transpose + fp16 convert ----------------
// in: [l][k][n] fp32 row-major; out: [l][n][k] fp16
__global__ void k_wconv(const float* __restrict__ w1,
                        const float* __restrict__ w2,
                        const float* __restrict__ w3)
{
    const int SET = LL * HH * HH;  // 98304
    int idx = blockIdx.x * blockDim.x + threadIdx.x;
    if (idx >= 3 * SET) return;
    int which = idx / SET;
    int r = idx - which * SET;
    int l = r >> 14;          // /16384
    int k = (r >> 7) & 127;
    int n = r & 127;
    const float* in = (which == 0) ? w1 : (which == 1) ? w2 : w3;
    __half* out = (which == 0) ? g_w1t : (which == 1) ? g_w2t : g_w3t;
    out[l * HH * HH + n * HH + k] = __float2half(in[r]);
}

// ---------------- CSR build ----------------
__global__ void k_zero(int n) {
    int i = blockIdx.x * blockDim.x + threadIdx.x;
    if (i < n) g_deg[i] = 0;
}

__global__ void k_prep(const int* __restrict__ ei, const float* __restrict__ pos, int E) {
    int e = blockIdx.x * blockDim.x + threadIdx.x;
    if (e >= E) return;
    int r = ei[e], c = ei[E + e];
    float dx = pos[r * 3 + 0] - pos[c * 3 + 0];
    float dy = pos[r * 3 + 1] - pos[c * 3 + 1];
    float dz = pos[r * 3 + 2] - pos[c * 3 + 2];
    float d = sqrtf(dx * dx + dy * dy + dz * dz);
    float u = d * TABSCALE;
    int k = (int)u;
    if (k > KTAB - 2) k = KTAB - 2;
    if (k < 0) k = 0;
    float t = u - (float)k;
    g_um[e] = r | (k << 14);
    g_ut[e] = t;
    atomicAdd(&g_deg[c], 1);
}

__global__ void __launch_bounds__(1024) k_scan(int n) {
    __shared__ int s[1024];
    const int PER = 10;
    int t = threadIdx.x;
    int base = t * PER;
    int local[PER];
    int sum = 0;
#pragma unroll
    for (int i = 0; i < PER; i++) {
        int v = (base + i < n) ? g_deg[base + i] : 0;
        local[i] = sum;
        sum += v;
    }
    s[t] = sum;
    __syncthreads();
    for (int off = 1; off < 1024; off <<= 1) {
        int v = s[t];
        if (t >= off) v += s[t - off];
        __syncthreads();
        s[t] = v;
        __syncthreads();
    }
    int offset = s[t] - sum;
#pragma unroll
    for (int i = 0; i < PER; i++) {
        if (base + i < n) {
            int st = offset + local[i];
            g_start[base + i]  = st;
            g_cursor[base + i] = st;
        }
    }
    if (t == 1023) g_start[n] = s[1023];
}

__global__ void k_scatter(const int* __restrict__ ei, int E) {
    int e = blockIdx.x * blockDim.x + threadIdx.x;
    if (e >= E) return;
    int c = ei[E + e];
    int p = atomicAdd(&g_cursor[c], 1);
    g_sm[p] = g_um[e];
    g_st[p] = g_ut[e];
}

// ---------------- embedding: h fp32 + fp16 copy ----------------
__global__ void k_embed(const int* __restrict__ z, const float* __restrict__ emb,
                        float* __restrict__ h, int N) {
    int idx = blockIdx.x * blockDim.x + threadIdx.x;  // over N*32 float4
    if (idx >= N * 32) return;
    int n = idx >> 5, q = idx & 31;
    float4 v = ((const float4*)emb)[z[n] * 32 + q];
    ((float4*)h)[idx] = v;
    uint2 p;
    __half2 h0 = __floats2half2_rn(v.x, v.y);
    __half2 h1 = __floats2half2_rn(v.z, v.w);
    p.x = *(unsigned int*)&h0;
    p.y = *(unsigned int*)&h1;
    ((uint2*)g_hh)[idx] = p;
}

// ---------------- message aggregation (gather, fp16 data, fp32 acc) --------
// one warp per target node. Warp is split into two 16-lane halves:
//   flane = lane & 15 : feature group (8 halves each -> 16*8 = 128 features)
//   esub  = lane >> 4 : which edge of the current pair this half processes
__global__ void __launch_bounds__(256) k_agg(int l, int N) {
    int warp = (blockIdx.x * 256 + threadIdx.x) >> 5;
    int lane = threadIdx.x & 31;
    if (warp >= N) return;
    const __half* __restrict__ tab = g_tab + (size_t)l * KTAB * HH;
    int beg = g_start[warp], end = g_start[warp + 1];
    const int flane = lane & 15;
    const int esub  = lane >> 4;
    float acc[8];
#pragma unroll
    for (int q = 0; q < 8; q++) acc[q] = 0.f;

    for (int e0 = beg; e0 < end; e0 += 32) {
        int idx = e0 + lane;
        int m = 0;
        float tt = 0.f;
        if (idx < end) { m = g_sm[idx]; tt = g_st[idx]; }
        int cnt = min(32, end - e0);
        for (int s = 0; s < cnt; s += 2) {
            int j = s + esub;                 // this half-warp's edge in the pair
            int   mj = __shfl_sync(0xffffffffu, m, j);
            float tj = __shfl_sync(0xffffffffu, tt, j);
            if (j < cnt) {
                int src = mj & 0x3FFF;
                int k   = mj >> 14;
                uint4 xr  = *(const uint4*)(g_xh + (size_t)src * HH + flane * 8);
                uint4 w0r = *(const uint4*)(tab + (size_t)k * HH + flane * 8);
                uint4 w1r = *(const uint4*)(tab + (size_t)(k + 1) * HH + flane * 8);
                __half2 t2 = __float2half2_rn(tj);
                const __half2* xv = (const __half2*)&xr;
                const __half2* a0 = (const __half2*)&w0r;
                const __half2* a1 = (const __half2*)&w1r;
#pragma unroll
                for (int q = 0; q < 4; q++) {
                    __half2 d = __hsub2(a1[q], a0[q]);
                    __half2 w = __hfma2(t2, d, a0[q]);
                    __half2 p = __hmul2(w, xv[q]);
                    float2 pf = __half22float2(p);
                    acc[q * 2 + 0] += pf.x;
                    acc[q * 2 + 1] += pf.y;
                }
            }
        }
    }
    // combine the two edge-halves (same features live in lane and lane^16)
#pragma unroll
    for (int q = 0; q < 8; q++)
        acc[q] += __shfl_xor_sync(0xffffffffu, acc[q], 16);

    if (esub == 0) {
        uint4 outv;
        __half2* op = (__half2*)&outv;
#pragma unroll
        for (int q = 0; q < 4; q++)
            op[q] = __floats2half2_rn(acc[q * 2], acc[q * 2 + 1]);
        *(uint4*)(g_aggh + (size_t)warp * HH + flane * 8) = outv;
    }
}

// ---------------- tensor-core GEMM: M x 128 x 128, fp16 in / fp32 acc ------
// Weights selected INSIDE device code (device globals must not be addressed
// from host — ATS silently maps the host shadow symbol => zeros).
// MODE 0: g_xh   = hh @ W1t^T                 (A = g_hh,   B = g_w1t[l])
// MODE 1: g_uh   = ssp(aggh @ W2t^T + bias)   (A = g_aggh, B = g_w2t[l])
// MODE 2: h     += uh @ W3t^T + bias; hh = h  (A = g_uh,   B = g_w3t[l])
template <int MODE>
__global__ void __launch_bounds__(256) gemm_mma(
    int l, const float* __restrict__ bias,
    float* __restrict__ hbuf, int M)
{
    __shared__ __align__(16) char smem_raw[49152];
    __half* As = (__half*)smem_raw;            // 64 x 128 (16 KB)
    __half* Bs = (__half*)(smem_raw + 16384);  // 128 x 128 [n][k] (32 KB)
    float*  Os = (float*)smem_raw;             // 64 x 128 fp32 (reused, 32 KB)

    const int tid = threadIdx.x;
    const int wid = tid >> 5;
    const int m0 = blockIdx.x * 64;

    const __half* A  = (MODE == 0) ? g_hh : (MODE == 1) ? g_aggh : g_uh;
    const __half* Bw = ((MODE == 0) ? g_w1t : (MODE == 1) ? g_w2t : g_w3t)
                       + (size_t)l * HH * HH;

    // load A tile (64 x 128 halves = 1024 uint4)
#pragma unroll
    for (int i = 0; i < 4; i++) {
        int lin = i * 256 + tid;           // uint4 index
        int r = lin >> 4, c = lin & 15;    // 16 uint4 per row
        int gr = m0 + r;
        uint4 v = make_uint4(0, 0, 0, 0);
        if (gr < M) v = *(const uint4*)(A + (size_t)gr * HH + c * 8);
        *(uint4*)(As + r * HH + c * 8) = v;
    }
    // load B (128 x 128 halves = 2048 uint4)
#pragma unroll
    for (int i = 0; i < 8; i++) {
        int lin = i * 256 + tid;
        *(uint4*)(Bs + lin * 8) = *(const uint4*)(Bw + lin * 8);
    }
    __syncthreads();

    // warp grid: 4 (m) x 2 (n); each warp: 16 rows x 64 cols
    const int wm = wid & 3;
    const int wn = wid >> 2;

    wmma::fragment<wmma::accumulator, 16, 16, 16, float> accf[4];
#pragma unroll
    for (int n = 0; n < 4; n++) wmma::fill_fragment(accf[n], 0.f);

#pragma unroll
    for (int ks = 0; ks < 8; ks++) {
        wmma::fragment<wmma::matrix_a, 16, 16, 16, __half, wmma::row_major> af;
        wmma::load_matrix_sync(af, As + (wm * 16) * HH + ks * 16, HH);
#pragma unroll
        for (int n = 0; n < 4; n++) {
            wmma::fragment<wmma::matrix_b, 16, 16, 16, __half, wmma::col_major> bf;
            wmma::load_matrix_sync(bf, Bs + (wn * 64 + n * 16) * HH + ks * 16, HH);
            wmma::mma_sync(accf[n], af, bf, accf[n]);
        }
    }
    __syncthreads();  // done reading As/Bs — safe to overwrite with Os
#pragma unroll
    for (int n = 0; n < 4; n++)
        wmma::store_matrix_sync(Os + (wm * 16) * HH + wn * 64 + n * 16,
                                accf[n], HH, wmma::mem_row_major);
    __syncthreads();

    // epilogue: 64 x 32 float4 = 2048, 8 per thread
#pragma unroll
    for (int i = 0; i < 8; i++) {
        int lin = i * 256 + tid;
        int r = lin >> 5, c4 = lin & 31;
        int gr = m0 + r;
        if (gr >= M) continue;
        float4 v = *(float4*)(Os + r * HH + c4 * 4);
        if (MODE >= 1) {
            const float4 bi = *(const float4*)(bias + c4 * 4);
            v.x += bi.x; v.y += bi.y; v.z += bi.z; v.w += bi.w;
        }
        if (MODE == 1) {
            v.x = sspf(v.x); v.y = sspf(v.y); v.z = sspf(v.z); v.w = sspf(v.w);
        }
        if (MODE == 2) {
            float4 o = *(float4*)(hbuf + (size_t)gr * HH + c4 * 4);
            v.x += o.x; v.y += o.y; v.z += o.z; v.w += o.w;
            *(float4*)(hbuf + (size_t)gr * HH + c4 * 4) = v;
        }
        // fp16 store (x / u / hh)
        __half* outh = (MODE == 0) ? g_xh : (MODE == 1) ? g_uh : g_hh;
        uint2 p;
        __half2 h0 = __floats2half2_rn(v.x, v.y);
        __half2 h1 = __floats2half2_rn(v.z, v.w);
        p.x = *(unsigned int*)&h0;
        p.y = *(unsigned int*)&h1;
        *(uint2*)(outh + (size_t)gr * HH + c4 * 4) = p;
    }
}

// ---------------- launch ----------------
extern "C" void kernel_launch(void* const* d_in, const int* in_sizes, int n_in,
                              void* d_out, int out_size)
{
    const int*   z      = (const int*)d_in[0];
    const float* pos    = (const float*)d_in[1];
    const int*   ei     = (const int*)d_in[2];
    const float* emb    = (const float*)d_in[3];
    const float* mlp_w1 = (const float*)d_in[4];
    const float* mlp_b1 = (const float*)d_in[5];
    const float* mlp_w2 = (const float*)d_in[6];
    const float* mlp_b2 = (const float*)d_in[7];
    const float* lin1_w = (const float*)d_in[8];
    const float* lin2_w = (const float*)d_in[9];
    const float* lin2_b = (const float*)d_in[10];
    const float* lin_w  = (const float*)d_in[11];
    const float* lin_b  = (const float*)d_in[12];

    const int N = in_sizes[0];
    const int E = in_sizes[2] / 2;
    float* h = (float*)d_out;

    k_zero<<<(N + 255) / 256, 256>>>(N);
    dim3 tg(KTAB / PTS, LL);
    k_table<<<tg, 128>>>(mlp_w1, mlp_b1, mlp_w2, mlp_b2);
    k_wconv<<<(3 * LL * HH * HH + 255) / 256, 256>>>(lin1_w, lin2_w, lin_w);
    k_prep<<<(E + 255) / 256, 256>>>(ei, pos, E);
    k_scan<<<1, 1024>>>(N);
    k_scatter<<<(E + 255) / 256, 256>>>(ei, E);
    k_embed<<<(N * 32 + 255) / 256, 256>>>(z, emb, h, N);

    const int gb = (N + 63) / 64;
    const int ga = (N + 7) / 8;   // one warp per node, 8 warps/block
    for (int l = 0; l < LL; l++) {
        gemm_mma<0><<<gb, 256>>>(l, nullptr, h, N);
        k_agg<<<ga, 256>>>(l, N);
        gemm_mma<1><<<gb, 256>>>(l, lin2_b + (size_t)l * HH, h, N);
        gemm_mma<2><<<gb, 256>>>(l, lin_b + (size_t)l * HH, h, N);
    }
}